// round 1
// baseline (speedup 1.0000x reference)
#include <cuda_runtime.h>
#include <cuda_bf16.h>
#include <cstdint>

#define Bb   8
#define Tt   4096
#define Dd   1024
#define Hh   16
#define DHh  64
#define UMAX 64

typedef long long ll;

// ---------------- scratch (static __device__, allocation-free) ----------------
__device__ float g_xs[Bb * UMAX * Dd];                       // gathered x rows
__device__ float g_Qs[Bb * UMAX * Dd];                       // xs @ Wq^T
__device__ float g_Qt[Bb * Hh * UMAX * Dd];                  // (Qs_h @ Wk_h) * scale
__device__ float g_sc[(size_t)Bb * Hh * UMAX * Tt];          // scores / attn (in place)
__device__ float g_wx[Bb * Hh * UMAX * Dd];                  // attn @ x
__device__ float g_ctx[Bb * Hh * UMAX * DHh];                // wx @ Wv_h^T
__device__ float g_cr[Bb * (UMAX + 1) * Dd];                 // ctx rows + mean row
__device__ float g_ys[Bb * (UMAX + 1) * Dd];                 // cr @ Wo^T

// ---------------- gather x rows at idx ----------------
__global__ __launch_bounds__(256) void gather_xs_k(float4* __restrict__ xs,
                                                   const float4* __restrict__ x,
                                                   const int* __restrict__ idx, int u) {
    int b = blockIdx.x / u, j = blockIdx.x % u;
    int t = idx[j];
    const float4* src = x + ((size_t)b * Tt + t) * (Dd / 4);
    float4* dst = xs + ((size_t)b * u + j) * (Dd / 4);
    dst[threadIdx.x] = src[threadIdx.x];
}

// ---------------- generic tiled GEMM: C = alpha * A(MxK) * op(B) ----------------
// NT: B is (N x K) row-major (op = B^T).  NN: B is (K x N) row-major.
// Tile: BM=64, BN=128, BK=16; 256 threads; 4x8 microtile via packed fma.rn.f32x2.
// grid.z = batch*nh + head; per-axis strides allow the (b,h) batched cases.
template <bool NT>
__global__ __launch_bounds__(256) void gemm_k(
    float* __restrict__ C, const float* __restrict__ A, const float* __restrict__ B,
    int M, int N, int K, int lda, int ldb, int ldc,
    ll sAb, ll sAh, ll sBb, ll sBh, ll sCb, ll sCh, int nh, float alpha) {
    int z = blockIdx.z;
    int bb = z / nh, hh = z - bb * nh;
    A += bb * sAb + hh * sAh;
    B += bb * sBb + hh * sBh;
    C += bb * sCb + hh * sCh;

    int m0 = blockIdx.y * 64, n0 = blockIdx.x * 128;
    __shared__ float As[16][64];
    __shared__ float Bs[16][128];

    int tid = threadIdx.x;
    int tm = tid >> 4;           // 0..15  -> rows tm*4 .. tm*4+3
    int tn = tid & 15;           // 0..15  -> cols tn*8 .. tn*8+7
    int ar = tid >> 2;           // 0..63  load row
    int ak = (tid & 3) << 2;     // k offset 0,4,8,12

    unsigned long long acc[2][8];
#pragma unroll
    for (int p = 0; p < 2; p++)
#pragma unroll
        for (int j = 0; j < 8; j++) acc[p][j] = 0ull;

    for (int k0 = 0; k0 < K; k0 += 16) {
        // A tile (M x 16), transposed into As[k][m]
        float4 av = make_float4(0.f, 0.f, 0.f, 0.f);
        if (m0 + ar < M) av = *(const float4*)(A + (size_t)(m0 + ar) * lda + (k0 + ak));
        As[ak + 0][ar] = av.x; As[ak + 1][ar] = av.y;
        As[ak + 2][ar] = av.z; As[ak + 3][ar] = av.w;

        if (NT) {
#pragma unroll
            for (int rr = 0; rr < 2; rr++) {
                int n = n0 + ar + rr * 64;
                float4 bv = make_float4(0.f, 0.f, 0.f, 0.f);
                if (n < N) bv = *(const float4*)(B + (size_t)n * ldb + (k0 + ak));
                Bs[ak + 0][ar + rr * 64] = bv.x; Bs[ak + 1][ar + rr * 64] = bv.y;
                Bs[ak + 2][ar + rr * 64] = bv.z; Bs[ak + 3][ar + rr * 64] = bv.w;
            }
        } else {
            int kk = tid >> 4, n8 = (tid & 15) << 3;
#pragma unroll
            for (int q = 0; q < 2; q++) {
                int n = n0 + n8 + q * 4;
                float4 bv = make_float4(0.f, 0.f, 0.f, 0.f);
                if (n < N) bv = *(const float4*)(B + (size_t)(k0 + kk) * ldb + n);
                *(float4*)&Bs[kk][n8 + q * 4] = bv;
            }
        }
        __syncthreads();

#pragma unroll
        for (int k = 0; k < 16; k++) {
            unsigned long long a0 = *(const unsigned long long*)&As[k][tm * 4];
            unsigned long long a1 = *(const unsigned long long*)&As[k][tm * 4 + 2];
            float4 blo = *(const float4*)&Bs[k][tn * 8];
            float4 bhi = *(const float4*)&Bs[k][tn * 8 + 4];
            float bv[8] = {blo.x, blo.y, blo.z, blo.w, bhi.x, bhi.y, bhi.z, bhi.w};
#pragma unroll
            for (int j = 0; j < 8; j++) {
                unsigned int bi = __float_as_uint(bv[j]);
                unsigned long long bp;
                asm("mov.b64 %0, {%1, %1};" : "=l"(bp) : "r"(bi));
                asm("fma.rn.f32x2 %0, %1, %2, %0;" : "+l"(acc[0][j]) : "l"(a0), "l"(bp));
                asm("fma.rn.f32x2 %0, %1, %2, %0;" : "+l"(acc[1][j]) : "l"(a1), "l"(bp));
            }
        }
        __syncthreads();
    }

#pragma unroll
    for (int p = 0; p < 2; p++) {
#pragma unroll
        for (int i = 0; i < 2; i++) {
            int m = m0 + tm * 4 + p * 2 + i;
            if (m < M) {
#pragma unroll
                for (int j = 0; j < 8; j++) {
                    int n = n0 + tn * 8 + j;
                    if (n < N) {
                        float2 c2 = *(float2*)&acc[p][j];
                        C[(size_t)m * ldc + n] = alpha * (i == 0 ? c2.x : c2.y);
                    }
                }
            }
        }
    }
}

// ---------------- row softmax (in place), row length Tt ----------------
__global__ __launch_bounds__(256) void softmax_k(float* __restrict__ s, int Tn) {
    __shared__ float red[256];
    size_t base = (size_t)blockIdx.x * Tn;
    int tid = threadIdx.x;
    float m = -3.4e38f;
    for (int t = tid; t < Tn; t += 256) m = fmaxf(m, s[base + t]);
    red[tid] = m; __syncthreads();
    for (int o = 128; o > 0; o >>= 1) {
        if (tid < o) red[tid] = fmaxf(red[tid], red[tid + o]);
        __syncthreads();
    }
    float mx = red[0];
    __syncthreads();
    float sum = 0.f;
    for (int t = tid; t < Tn; t += 256) {
        float e = __expf(s[base + t] - mx);
        s[base + t] = e;
        sum += e;
    }
    red[tid] = sum; __syncthreads();
    for (int o = 128; o > 0; o >>= 1) {
        if (tid < o) red[tid] += red[tid + o];
        __syncthreads();
    }
    float inv = 1.f / red[0];
    for (int t = tid; t < Tn; t += 256) s[base + t] *= inv;
}

// ---------------- ctx -> per-(b,t)-row layout + mean row ----------------
__global__ __launch_bounds__(64) void ctxrow_mean_k(float* __restrict__ cr,
                                                    const float* __restrict__ ctx, int u) {
    int b = blockIdx.x, h = blockIdx.y, d = threadIdx.x;
    float s = 0.f;
    for (int j = 0; j < u; j++) {
        float v = ctx[((size_t)(b * Hh + h) * u + j) * DHh + d];
        cr[((size_t)b * (u + 1) + j) * Dd + h * DHh + d] = v;
        s += v;
    }
    cr[((size_t)b * (u + 1) + u) * Dd + h * DHh + d] = s / (float)u;
}

// ---------------- broadcast fill with mean-row output + bias ----------------
__global__ __launch_bounds__(256) void fill_k(float4* __restrict__ y,
                                              const float4* __restrict__ ys,
                                              const float4* __restrict__ bo, int u) {
    int b = blockIdx.x / Tt;
    float4 v = ys[((size_t)b * (u + 1) + u) * 256 + threadIdx.x];
    float4 bb = bo[threadIdx.x];
    y[(size_t)blockIdx.x * 256 + threadIdx.x] =
        make_float4(v.x + bb.x, v.y + bb.y, v.z + bb.z, v.w + bb.w);
}

// ---------------- scatter exact rows at idx ----------------
__global__ __launch_bounds__(256) void scatter_k(float4* __restrict__ y,
                                                 const float4* __restrict__ ys,
                                                 const float4* __restrict__ bo,
                                                 const int* __restrict__ idx, int u) {
    int b = blockIdx.x, j = blockIdx.y;
    int t = idx[j];
    float4 v = ys[((size_t)b * (u + 1) + j) * 256 + threadIdx.x];
    float4 bb = bo[threadIdx.x];
    y[((size_t)b * Tt + t) * 256 + threadIdx.x] =
        make_float4(v.x + bb.x, v.y + bb.y, v.z + bb.z, v.w + bb.w);
}

// ---------------- launch ----------------
extern "C" void kernel_launch(void* const* d_in, const int* in_sizes, int n_in,
                              void* d_out, int out_size) {
    const float* x  = (const float*)d_in[0];
    const float* Wq = (const float*)d_in[1];
    const float* Wk = (const float*)d_in[2];
    const float* Wv = (const float*)d_in[3];
    const float* Wo = (const float*)d_in[4];
    const float* bo = (const float*)d_in[5];
    const int* idx  = (const int*)d_in[6];
    int u = in_sizes[6];
    if (u > UMAX) u = UMAX;
    if (u < 1) u = 1;
    float* y = (float*)d_out;

    float *xs, *Qs, *Qt, *sc, *wx, *ctx, *cr, *ys;
    cudaGetSymbolAddress((void**)&xs,  g_xs);
    cudaGetSymbolAddress((void**)&Qs,  g_Qs);
    cudaGetSymbolAddress((void**)&Qt,  g_Qt);
    cudaGetSymbolAddress((void**)&sc,  g_sc);
    cudaGetSymbolAddress((void**)&wx,  g_wx);
    cudaGetSymbolAddress((void**)&ctx, g_ctx);
    cudaGetSymbolAddress((void**)&cr,  g_cr);
    cudaGetSymbolAddress((void**)&ys,  g_ys);

    const int Hu = Hh * u;
    const float scale = 0.125f;  // 1/sqrt(64)

    // 1) gather x rows at idx
    gather_xs_k<<<Bb * u, 256>>>((float4*)xs, (const float4*)x, idx, u);

    // 2) Qs = xs @ Wq^T   (M=B*u, N=D, K=D), single batch
    gemm_k<true><<<dim3(Dd / 128, (Bb * u + 63) / 64, 1), 256>>>(
        Qs, xs, Wq, Bb * u, Dd, Dd, Dd, Dd, Dd, 0, 0, 0, 0, 0, 0, 1, 1.f);

    // 3) Qt[b,h] = scale * Qs[b,:,hDH:hDH+DH] @ Wk_h   (NN, M=u, N=D, K=DH)
    gemm_k<false><<<dim3(Dd / 128, (u + 63) / 64, Bb * Hh), 256>>>(
        Qt, Qs, Wk, u, Dd, DHh, Dd, Dd, Dd,
        (ll)u * Dd, (ll)DHh, 0, (ll)DHh * Dd, (ll)Hu * Dd, (ll)u * Dd, Hh, scale);

    // 4) scores[b] = Qt[b] @ x[b]^T   (NT, M=H*u, N=T, K=D)  -- 44 GF
    gemm_k<true><<<dim3(Tt / 128, (Hu + 63) / 64, Bb), 256>>>(
        sc, Qt, x, Hu, Tt, Dd, Dd, Dd, Tt,
        (ll)Hu * Dd, 0, (ll)Tt * Dd, 0, (ll)Hu * Tt, 0, 1, 1.f);

    // 5) softmax rows
    softmax_k<<<Bb * Hu, 256>>>(sc, Tt);

    // 6) wx[b] = attn[b] @ x[b]   (NN, M=H*u, N=D, K=T)  -- 44 GF
    gemm_k<false><<<dim3(Dd / 128, (Hu + 63) / 64, Bb), 256>>>(
        wx, sc, x, Hu, Dd, Tt, Tt, Dd, Dd,
        (ll)Hu * Tt, 0, (ll)Tt * Dd, 0, (ll)Hu * Dd, 0, 1, 1.f);

    // 7) ctx[b,h] = wx[b,h] @ Wv_h^T   (NT, M=u, N=DH, K=D)
    gemm_k<true><<<dim3(1, (u + 63) / 64, Bb * Hh), 256>>>(
        ctx, wx, Wv, u, DHh, Dd, Dd, Dd, DHh,
        (ll)Hu * Dd, (ll)u * Dd, 0, (ll)DHh * Dd, (ll)Hu * DHh, (ll)u * DHh, Hh, 1.f);

    // 8) reorder ctx to per-token rows, append mean row
    ctxrow_mean_k<<<dim3(Bb, Hh), 64>>>(cr, ctx, u);

    // 9) ys = cr @ Wo^T   (NT, M=u+1, N=D, K=D)
    gemm_k<true><<<dim3(Dd / 128, (u + 64) / 64, Bb), 256>>>(
        ys, cr, Wo, u + 1, Dd, Dd, Dd, Dd, Dd,
        (ll)(u + 1) * Dd, 0, 0, 0, (ll)(u + 1) * Dd, 0, 1, 1.f);

    // 10) broadcast mean output everywhere, then overwrite idx rows
    fill_k<<<Bb * Tt, 256>>>((float4*)y, (const float4*)ys, (const float4*)bo, u);
    scatter_k<<<dim3(Bb, u), 256>>>((float4*)y, (const float4*)ys, (const float4*)bo, idx, u);
}

// round 5
// speedup vs baseline: 2.2666x; 2.2666x over previous
#include <cuda_runtime.h>
#include <cuda_bf16.h>
#include <cstdint>

#define Bb   8
#define Tt   4096
#define Dd   1024
#define Hh   16
#define DHh  64
#define UMAX 64
#define MPMAX 1024

typedef long long ll;
typedef __nv_bfloat16 bf16;

// ---------------- scratch (static __device__, allocation-free) ----------------
__device__ float g_xs[Bb * UMAX * Dd];
__device__ float g_Qs[Bb * UMAX * Dd];
__device__ float g_Qt[Bb * Hh * UMAX * Dd];
__device__ bf16  g_Qth[(size_t)Bb * MPMAX * Dd];
__device__ bf16  g_Qtl[(size_t)Bb * MPMAX * Dd];
__device__ bf16  g_xh[(size_t)Bb * Tt * Dd];
__device__ bf16  g_xl[(size_t)Bb * Tt * Dd];
__device__ bf16  g_xth[(size_t)Bb * Dd * Tt];
__device__ bf16  g_xtl[(size_t)Bb * Dd * Tt];
__device__ float g_sc[(size_t)Bb * MPMAX * Tt];
__device__ bf16  g_ah[(size_t)Bb * MPMAX * Tt];
__device__ bf16  g_al[(size_t)Bb * MPMAX * Tt];
__device__ float g_wx[(size_t)Bb * MPMAX * Dd];
__device__ float g_ctx[Bb * Hh * UMAX * DHh];
__device__ float g_cr[Bb * (UMAX + 1) * Dd];
__device__ float g_ys[Bb * (UMAX + 1) * Dd];

// ---------------- PTX helpers (sm_80/sm_90 portable only) ----------------
__device__ __forceinline__ uint32_t smem_u32(const void* p) {
    uint32_t a;
    asm("{ .reg .u64 t; cvta.to.shared.u64 t, %1; cvt.u32.u64 %0, t; }" : "=r"(a) : "l"(p));
    return a;
}
__device__ __forceinline__ void cp_async16(uint32_t s, const void* g) {
    asm volatile("cp.async.cg.shared.global [%0], [%1], 16;" :: "r"(s), "l"(g) : "memory");
}
__device__ __forceinline__ void ldsm_x4(uint32_t* r, uint32_t a) {
    asm volatile("ldmatrix.sync.aligned.m8n8.x4.shared.b16 {%0,%1,%2,%3}, [%4];"
                 : "=r"(r[0]), "=r"(r[1]), "=r"(r[2]), "=r"(r[3]) : "r"(a));
}
__device__ __forceinline__ void ldsm_x2(uint32_t* r, uint32_t a) {
    asm volatile("ldmatrix.sync.aligned.m8n8.x2.shared.b16 {%0,%1}, [%2];"
                 : "=r"(r[0]), "=r"(r[1]) : "r"(a));
}
__device__ __forceinline__ void mma16816(float* c, const uint32_t* a, const uint32_t* b) {
    asm volatile(
        "mma.sync.aligned.m16n8k16.row.col.f32.bf16.bf16.f32 "
        "{%0,%1,%2,%3}, {%4,%5,%6,%7}, {%8,%9}, {%0,%1,%2,%3};"
        : "+f"(c[0]), "+f"(c[1]), "+f"(c[2]), "+f"(c[3])
        : "r"(a[0]), "r"(a[1]), "r"(a[2]), "r"(a[3]), "r"(b[0]), "r"(b[1]));
}

// ============ warp-MMA GEMM: C(fp32, mp x ldc) += 3-pass split(A) @ split(B)^T ============
// A: (M x Kt) row-major bf16 hi/lo.  B: (N x Kt) row-major bf16 hi/lo (i.e. op(B)=B^T).
// Block 128x128, BK=32, 8 warps (2x4), warp tile 64x32, 4-stage cp.async pipeline.
#define BMt 128
#define BNt 128
#define APAD 40                   // padded row stride in elems (80B -> conflict-free ldmatrix)
#define A_ST (BMt * APAD * 2)     // 10240 B
#define B_ST (BNt * APAD * 2)     // 10240 B
#define STG_SZ (A_ST + B_ST)      // 20480 B
#define NSTAGE 4

__global__ __launch_bounds__(256, 2) void mma_gemm_k(
    float* __restrict__ C,
    const bf16* __restrict__ Ah, const bf16* __restrict__ Al,
    const bf16* __restrict__ Bh, const bf16* __restrict__ Bl,
    int Kt, int ldc, ll sAb, ll sBb, ll sCb) {
    extern __shared__ char smem[];
    uint32_t sbase = smem_u32(smem);
    int tid = threadIdx.x, wid = tid >> 5, lane = tid & 31;
    int b = blockIdx.z;
    int m0 = blockIdx.y * BMt, n0 = blockIdx.x * BNt;

    const bf16* A0 = Ah + (size_t)b * sAb + (size_t)m0 * Kt;
    const bf16* A1 = Al + (size_t)b * sAb + (size_t)m0 * Kt;
    const bf16* B0 = Bh + (size_t)b * sBb + (size_t)n0 * Kt;
    const bf16* B1 = Bl + (size_t)b * sBb + (size_t)n0 * Kt;

    // ---- load mapping: 512 16B-chunks per operand tile, 2 per thread ----
    int lrow = tid >> 2;          // 0..63
    int lkc  = tid & 3;           // 0..3  (8-elem groups within BK=32)
    size_t   gA0 = (size_t)lrow * Kt + lkc * 8;
    size_t   gA1 = gA0 + (size_t)64 * Kt;
    uint32_t sA0 = lrow * 80 + lkc * 16;
    uint32_t sA1 = sA0 + 64 * 80;

    // ---- ldmatrix per-lane offsets ----
    int warp_m = wid >> 2, warp_n = wid & 3;
    uint32_t aoff[4], boff[4];
#pragma unroll
    for (int i = 0; i < 4; i++) {
        int row = warp_m * 64 + i * 16 + (lane & 7) + ((lane >> 3) & 1) * 8;
        int col = (lane >> 4) * 8;
        aoff[i] = (row * APAD + col) * 2;
    }
#pragma unroll
    for (int j = 0; j < 4; j++) {
        int row = warp_n * 32 + j * 8 + (lane & 7);
        int col = ((lane >> 3) & 1) * 8;
        boff[j] = (row * APAD + col) * 2;
    }

    float acc[4][4][4];
#pragma unroll
    for (int i = 0; i < 4; i++)
#pragma unroll
        for (int j = 0; j < 4; j++)
#pragma unroll
            for (int q = 0; q < 4; q++) acc[i][j][q] = 0.f;

    const int Kc = Kt >> 5;       // chunks of BK=32 per pass
    const int NC = 3 * Kc;        // 3 passes: AhBh, AhBl, AlBh

#define ISSUE(c_) do {                                                        \
    int p_ = (c_) / Kc, kc_ = (c_) - p_ * Kc;                                 \
    const bf16* Ap_ = (p_ < 2) ? A0 : A1;                                     \
    const bf16* Bp_ = (p_ == 1) ? B1 : B0;                                    \
    const bf16* Ak_ = Ap_ + kc_ * 32;                                         \
    const bf16* Bk_ = Bp_ + kc_ * 32;                                         \
    uint32_t st_ = sbase + ((c_) % NSTAGE) * STG_SZ;                          \
    cp_async16(st_ + sA0, Ak_ + gA0);                                         \
    cp_async16(st_ + sA1, Ak_ + gA1);                                         \
    cp_async16(st_ + A_ST + sA0, Bk_ + gA0);                                  \
    cp_async16(st_ + A_ST + sA1, Bk_ + gA1);                                  \
    asm volatile("cp.async.commit_group;" ::: "memory");                      \
} while (0)

    ISSUE(0); ISSUE(1); ISSUE(2);

    for (int c = 0; c < NC; c++) {
        if (c + 3 < NC) ISSUE(c + 3);
        if (c + 3 < NC)      asm volatile("cp.async.wait_group 3;" ::: "memory");
        else if (c + 2 < NC) asm volatile("cp.async.wait_group 2;" ::: "memory");
        else if (c + 1 < NC) asm volatile("cp.async.wait_group 1;" ::: "memory");
        else                 asm volatile("cp.async.wait_group 0;" ::: "memory");
        __syncthreads();

        uint32_t sa = sbase + (c % NSTAGE) * STG_SZ;
#pragma unroll
        for (int kk = 0; kk < 2; kk++) {
            uint32_t afr[4][4], bfr[4][2];
#pragma unroll
            for (int i = 0; i < 4; i++) ldsm_x4(afr[i], sa + aoff[i] + kk * 32);
#pragma unroll
            for (int j = 0; j < 4; j++) ldsm_x2(bfr[j], sa + A_ST + boff[j] + kk * 32);
#pragma unroll
            for (int i = 0; i < 4; i++)
#pragma unroll
                for (int j = 0; j < 4; j++) mma16816(acc[i][j], afr[i], bfr[j]);
        }
        __syncthreads();
    }

    // ---- epilogue: direct float2 stores ----
    float* Cb = C + (size_t)b * sCb;
#pragma unroll
    for (int i = 0; i < 4; i++) {
        int m = m0 + warp_m * 64 + i * 16 + (lane >> 2);
#pragma unroll
        for (int j = 0; j < 4; j++) {
            int n = n0 + warp_n * 32 + j * 8 + (lane & 3) * 2;
            *(float2*)&Cb[(size_t)m * ldc + n]       = make_float2(acc[i][j][0], acc[i][j][1]);
            *(float2*)&Cb[(size_t)(m + 8) * ldc + n] = make_float2(acc[i][j][2], acc[i][j][3]);
        }
    }
}

// ---------------- bf16 split helper ----------------
__device__ __forceinline__ void split2(float v, bf16& h, bf16& l) {
    h = __float2bfloat16(v);
    l = __float2bfloat16(v - __bfloat162float(h));
}

// ---------------- x -> bf16 hi/lo (straight + transposed) ----------------
__global__ __launch_bounds__(256) void convx_k(const float* __restrict__ x,
                                               bf16* __restrict__ xh, bf16* __restrict__ xl,
                                               bf16* __restrict__ xth, bf16* __restrict__ xtl) {
    __shared__ float ts[32][33];
    int b = blockIdx.z;
    int t0 = blockIdx.x * 32, d0 = blockIdx.y * 32;
    int tx = threadIdx.x & 31, ty = threadIdx.x >> 5;
#pragma unroll
    for (int i = 0; i < 4; i++) {
        int t = ty * 4 + i;
        size_t o = ((size_t)b * Tt + t0 + t) * Dd + d0 + tx;
        float v = x[o];
        ts[t][tx] = v;
        bf16 h, l; split2(v, h, l);
        xh[o] = h; xl[o] = l;
    }
    __syncthreads();
#pragma unroll
    for (int i = 0; i < 4; i++) {
        int d = ty * 4 + i;
        float v = ts[tx][d];
        bf16 h, l; split2(v, h, l);
        size_t o = ((size_t)b * Dd + d0 + d) * Tt + t0 + tx;
        xth[o] = h; xtl[o] = l;
    }
}

// ---------------- Qt fp32 -> padded bf16 hi/lo ----------------
__global__ __launch_bounds__(256) void qtconv_k(const float* __restrict__ Qt,
                                                bf16* __restrict__ Qh, bf16* __restrict__ Ql,
                                                int Hu, int mp) {
    int r = blockIdx.x, b = blockIdx.y;
    const float* src = Qt + ((size_t)b * Hu + r) * Dd;
    size_t dst = ((size_t)b * mp + r) * Dd;
    for (int d = threadIdx.x; d < Dd; d += 256) {
        float v = (r < Hu) ? src[d] : 0.f;
        bf16 h, l; split2(v, h, l);
        Qh[dst + d] = h; Ql[dst + d] = l;
    }
}

// ---------------- gather x rows at idx ----------------
__global__ __launch_bounds__(256) void gather_xs_k(float4* __restrict__ xs,
                                                   const float4* __restrict__ x,
                                                   const int* __restrict__ idx, int u) {
    int b = blockIdx.x / u, j = blockIdx.x % u;
    int t = idx[j];
    const float4* src = x + ((size_t)b * Tt + t) * (Dd / 4);
    float4* dst = xs + ((size_t)b * u + j) * (Dd / 4);
    dst[threadIdx.x] = src[threadIdx.x];
}

// ---------------- small fp32 SIMT GEMM ----------------
template <bool NT>
__global__ __launch_bounds__(256) void gemm_k(
    float* __restrict__ C, const float* __restrict__ A, const float* __restrict__ B,
    int M, int N, int K, int lda, int ldb, int ldc,
    ll sAb, ll sAh, ll sBb, ll sBh, ll sCb, ll sCh, int nh, float alpha) {
    int z = blockIdx.z;
    int bb = z / nh, hh = z - bb * nh;
    A += bb * sAb + hh * sAh;
    B += bb * sBb + hh * sBh;
    C += bb * sCb + hh * sCh;

    int m0 = blockIdx.y * 64, n0 = blockIdx.x * 128;
    __shared__ float As[16][64];
    __shared__ float Bs[16][128];

    int tid = threadIdx.x;
    int tm = tid >> 4, tn = tid & 15;
    int ar = tid >> 2, ak = (tid & 3) << 2;

    unsigned long long acc[2][8];
#pragma unroll
    for (int p = 0; p < 2; p++)
#pragma unroll
        for (int j = 0; j < 8; j++) acc[p][j] = 0ull;

    for (int k0 = 0; k0 < K; k0 += 16) {
        float4 av = make_float4(0.f, 0.f, 0.f, 0.f);
        if (m0 + ar < M) av = *(const float4*)(A + (size_t)(m0 + ar) * lda + (k0 + ak));
        As[ak + 0][ar] = av.x; As[ak + 1][ar] = av.y;
        As[ak + 2][ar] = av.z; As[ak + 3][ar] = av.w;

        if (NT) {
#pragma unroll
            for (int rr = 0; rr < 2; rr++) {
                int n = n0 + ar + rr * 64;
                float4 bv = make_float4(0.f, 0.f, 0.f, 0.f);
                if (n < N) bv = *(const float4*)(B + (size_t)n * ldb + (k0 + ak));
                Bs[ak + 0][ar + rr * 64] = bv.x; Bs[ak + 1][ar + rr * 64] = bv.y;
                Bs[ak + 2][ar + rr * 64] = bv.z; Bs[ak + 3][ar + rr * 64] = bv.w;
            }
        } else {
            int kk = tid >> 4, n8 = (tid & 15) << 3;
#pragma unroll
            for (int q = 0; q < 2; q++) {
                int n = n0 + n8 + q * 4;
                float4 bv = make_float4(0.f, 0.f, 0.f, 0.f);
                if (n < N) bv = *(const float4*)(B + (size_t)(k0 + kk) * ldb + n);
                *(float4*)&Bs[kk][n8 + q * 4] = bv;
            }
        }
        __syncthreads();

#pragma unroll
        for (int k = 0; k < 16; k++) {
            unsigned long long a0 = *(const unsigned long long*)&As[k][tm * 4];
            unsigned long long a1 = *(const unsigned long long*)&As[k][tm * 4 + 2];
            float4 blo = *(const float4*)&Bs[k][tn * 8];
            float4 bhi = *(const float4*)&Bs[k][tn * 8 + 4];
            float bv[8] = {blo.x, blo.y, blo.z, blo.w, bhi.x, bhi.y, bhi.z, bhi.w};
#pragma unroll
            for (int j = 0; j < 8; j++) {
                unsigned int bi = __float_as_uint(bv[j]);
                unsigned long long bp;
                asm("mov.b64 %0, {%1, %1};" : "=l"(bp) : "r"(bi));
                asm("fma.rn.f32x2 %0, %1, %2, %0;" : "+l"(acc[0][j]) : "l"(a0), "l"(bp));
                asm("fma.rn.f32x2 %0, %1, %2, %0;" : "+l"(acc[1][j]) : "l"(a1), "l"(bp));
            }
        }
        __syncthreads();
    }

#pragma unroll
    for (int p = 0; p < 2; p++) {
#pragma unroll
        for (int i = 0; i < 2; i++) {
            int m = m0 + tm * 4 + p * 2 + i;
            if (m < M) {
#pragma unroll
                for (int j = 0; j < 8; j++) {
                    int n = n0 + tn * 8 + j;
                    if (n < N) {
                        float2 c2 = *(float2*)&acc[p][j];
                        C[(size_t)m * ldc + n] = alpha * (i == 0 ? c2.x : c2.y);
                    }
                }
            }
        }
    }
}

// ---------------- softmax rows + write attn bf16 hi/lo ----------------
__global__ __launch_bounds__(256) void softmax_k(float* __restrict__ s,
                                                 bf16* __restrict__ ah, bf16* __restrict__ al,
                                                 int Hu, int mp) {
    __shared__ float red[256];
    int b = blockIdx.x / Hu, r = blockIdx.x % Hu;
    size_t base = ((size_t)b * mp + r) * Tt;
    int tid = threadIdx.x;
    float m = -3.4e38f;
    for (int t = tid; t < Tt; t += 256) m = fmaxf(m, s[base + t]);
    red[tid] = m; __syncthreads();
    for (int o = 128; o > 0; o >>= 1) {
        if (tid < o) red[tid] = fmaxf(red[tid], red[tid + o]);
        __syncthreads();
    }
    float mx = red[0];
    __syncthreads();
    float sum = 0.f;
    for (int t = tid; t < Tt; t += 256) {
        float e = __expf(s[base + t] - mx);
        s[base + t] = e;
        sum += e;
    }
    red[tid] = sum; __syncthreads();
    for (int o = 128; o > 0; o >>= 1) {
        if (tid < o) red[tid] += red[tid + o];
        __syncthreads();
    }
    float inv = 1.f / red[0];
    for (int t = tid; t < Tt; t += 256) {
        float p = s[base + t] * inv;
        bf16 h, l; split2(p, h, l);
        ah[base + t] = h; al[base + t] = l;
    }
}

// ---------------- ctx -> per-token rows + mean row ----------------
__global__ __launch_bounds__(64) void ctxrow_mean_k(float* __restrict__ cr,
                                                    const float* __restrict__ ctx, int u) {
    int b = blockIdx.x, h = blockIdx.y, d = threadIdx.x;
    float s = 0.f;
    for (int j = 0; j < u; j++) {
        float v = ctx[((size_t)(b * Hh + h) * u + j) * DHh + d];
        cr[((size_t)b * (u + 1) + j) * Dd + h * DHh + d] = v;
        s += v;
    }
    cr[((size_t)b * (u + 1) + u) * Dd + h * DHh + d] = s / (float)u;
}

// ---------------- broadcast fill + scatter ----------------
__global__ __launch_bounds__(256) void fill_k(float4* __restrict__ y,
                                              const float4* __restrict__ ys,
                                              const float4* __restrict__ bo, int u) {
    int b = blockIdx.x / Tt;
    float4 v = ys[((size_t)b * (u + 1) + u) * 256 + threadIdx.x];
    float4 bb = bo[threadIdx.x];
    y[(size_t)blockIdx.x * 256 + threadIdx.x] =
        make_float4(v.x + bb.x, v.y + bb.y, v.z + bb.z, v.w + bb.w);
}
__global__ __launch_bounds__(256) void scatter_k(float4* __restrict__ y,
                                                 const float4* __restrict__ ys,
                                                 const float4* __restrict__ bo,
                                                 const int* __restrict__ idx, int u) {
    int b = blockIdx.x, j = blockIdx.y;
    int t = idx[j];
    float4 v = ys[((size_t)b * (u + 1) + j) * 256 + threadIdx.x];
    float4 bb = bo[threadIdx.x];
    y[((size_t)b * Tt + t) * 256 + threadIdx.x] =
        make_float4(v.x + bb.x, v.y + bb.y, v.z + bb.z, v.w + bb.w);
}

// ---------------- launch ----------------
extern "C" void kernel_launch(void* const* d_in, const int* in_sizes, int n_in,
                              void* d_out, int out_size) {
    const float* x  = (const float*)d_in[0];
    const float* Wq = (const float*)d_in[1];
    const float* Wk = (const float*)d_in[2];
    const float* Wv = (const float*)d_in[3];
    const float* Wo = (const float*)d_in[4];
    const float* bo = (const float*)d_in[5];
    const int* idx  = (const int*)d_in[6];
    int u = in_sizes[6];
    if (u > UMAX) u = UMAX;
    if (u < 1) u = 1;
    float* y = (float*)d_out;

    float *xs, *Qs, *Qt, *sc, *wx, *ctx, *cr, *ys;
    bf16 *Qth, *Qtl, *xh, *xl, *xth, *xtl, *ah, *al;
    cudaGetSymbolAddress((void**)&xs,  g_xs);
    cudaGetSymbolAddress((void**)&Qs,  g_Qs);
    cudaGetSymbolAddress((void**)&Qt,  g_Qt);
    cudaGetSymbolAddress((void**)&sc,  g_sc);
    cudaGetSymbolAddress((void**)&wx,  g_wx);
    cudaGetSymbolAddress((void**)&ctx, g_ctx);
    cudaGetSymbolAddress((void**)&cr,  g_cr);
    cudaGetSymbolAddress((void**)&ys,  g_ys);
    cudaGetSymbolAddress((void**)&Qth, g_Qth);
    cudaGetSymbolAddress((void**)&Qtl, g_Qtl);
    cudaGetSymbolAddress((void**)&xh,  g_xh);
    cudaGetSymbolAddress((void**)&xl,  g_xl);
    cudaGetSymbolAddress((void**)&xth, g_xth);
    cudaGetSymbolAddress((void**)&xtl, g_xtl);
    cudaGetSymbolAddress((void**)&ah,  g_ah);
    cudaGetSymbolAddress((void**)&al,  g_al);

    const int Hu = Hh * u;
    const int mp = ((Hu + 127) / 128) * 128;
    const float scale = 0.125f;

    const int smem_sz = NSTAGE * STG_SZ;  // 81920
    cudaFuncSetAttribute(mma_gemm_k, cudaFuncAttributeMaxDynamicSharedMemorySize, smem_sz);

    // 0) x -> bf16 hi/lo, straight + transposed
    convx_k<<<dim3(Tt / 32, Dd / 32, Bb), 256>>>(x, xh, xl, xth, xtl);

    // 1) gather x rows at idx
    gather_xs_k<<<Bb * u, 256>>>((float4*)xs, (const float4*)x, idx, u);

    // 2) Qs = xs @ Wq^T
    gemm_k<true><<<dim3(Dd / 128, (Bb * u + 63) / 64, 1), 256>>>(
        Qs, xs, Wq, Bb * u, Dd, Dd, Dd, Dd, Dd, 0, 0, 0, 0, 0, 0, 1, 1.f);

    // 3) Qt[b,h] = scale * Qs[b,:,hDH:] @ Wk_h
    gemm_k<false><<<dim3(Dd / 128, (u + 63) / 64, Bb * Hh), 256>>>(
        Qt, Qs, Wk, u, Dd, DHh, Dd, Dd, Dd,
        (ll)u * Dd, (ll)DHh, 0, (ll)DHh * Dd, (ll)Hu * Dd, (ll)u * Dd, Hh, scale);

    // 3b) Qt -> padded bf16 hi/lo
    qtconv_k<<<dim3(mp, Bb), 256>>>(Qt, Qth, Qtl, Hu, mp);

    // 4) scores[b] = Qt[b] @ x[b]^T   (warp-MMA, bf16 3-pass)
    mma_gemm_k<<<dim3(Tt / BNt, mp / BMt, Bb), 256, smem_sz>>>(
        sc, Qth, Qtl, xh, xl, Dd, Tt, (ll)mp * Dd, (ll)Tt * Dd, (ll)mp * Tt);

    // 5) softmax -> attn bf16 hi/lo
    softmax_k<<<Bb * Hu, 256>>>(sc, ah, al, Hu, mp);

    // 6) wx[b] = attn[b] @ x[b]   (warp-MMA, bf16 3-pass; B = x^T layout)
    mma_gemm_k<<<dim3(Dd / BNt, mp / BMt, Bb), 256, smem_sz>>>(
        wx, ah, al, xth, xtl, Tt, Dd, (ll)mp * Tt, (ll)Dd * Tt, (ll)mp * Dd);

    // 7) ctx[b,h] = wx[b,h] @ Wv_h^T
    gemm_k<true><<<dim3(1, (u + 63) / 64, Bb * Hh), 256>>>(
        ctx, wx, Wv, u, DHh, Dd, Dd, Dd, DHh,
        (ll)mp * Dd, (ll)u * Dd, 0, (ll)DHh * Dd, (ll)Hu * DHh, (ll)u * DHh, Hh, 1.f);

    // 8) reorder ctx + mean row
    ctxrow_mean_k<<<dim3(Bb, Hh), 64>>>(cr, ctx, u);

    // 9) ys = cr @ Wo^T
    gemm_k<true><<<dim3(Dd / 128, (u + 64) / 64, Bb), 256>>>(
        ys, cr, Wo, u + 1, Dd, Dd, Dd, Dd, Dd,
        (ll)(u + 1) * Dd, 0, 0, 0, (ll)(u + 1) * Dd, 0, 1, 1.f);

    // 10) broadcast + scatter
    fill_k<<<Bb * Tt, 256>>>((float4*)y, (const float4*)ys, (const float4*)bo, u);
    scatter_k<<<dim3(Bb, u), 256>>>((float4*)y, (const float4*)ys, (const float4*)bo, idx, u);
}

// round 7
// speedup vs baseline: 2.7086x; 1.1950x over previous
#include <cuda_runtime.h>
#include <cuda_bf16.h>
#include <cstdint>

#define Bb   8
#define Tt   4096
#define Dd   1024
#define Hh   16
#define DHh  64
#define UMAX 64
#define MPMAX 1024

typedef long long ll;
typedef __nv_bfloat16 bf16;

// ---------------- scratch (static __device__, allocation-free) ----------------
__device__ bf16  g_xsh[Bb * UMAX * Dd];
__device__ bf16  g_xsl[Bb * UMAX * Dd];
__device__ float g_Qs[Bb * UMAX * Dd];
__device__ bf16  g_Wqh[Dd * Dd];
__device__ bf16  g_Wql[Dd * Dd];
__device__ bf16  g_Qth[(size_t)Bb * MPMAX * Dd];
__device__ bf16  g_Qtl[(size_t)Bb * MPMAX * Dd];
__device__ bf16  g_xh[(size_t)Bb * Tt * Dd];
__device__ bf16  g_xl[(size_t)Bb * Tt * Dd];
__device__ bf16  g_xth[(size_t)Bb * Dd * Tt];
__device__ bf16  g_xtl[(size_t)Bb * Dd * Tt];
__device__ float g_sc[(size_t)Bb * MPMAX * Tt];
__device__ bf16  g_ah[(size_t)Bb * MPMAX * Tt];
__device__ bf16  g_al[(size_t)Bb * MPMAX * Tt];
__device__ float g_rsum[Bb * Hh * UMAX];
__device__ float g_wx[(size_t)Bb * MPMAX * Dd];
__device__ float g_ctx[Bb * Hh * UMAX * DHh];
__device__ float g_cr[Bb * (UMAX + 1) * Dd];
__device__ float g_ys[Bb * (UMAX + 1) * Dd];

// ---------------- PTX helpers (sm_80/sm_90 portable only) ----------------
__device__ __forceinline__ uint32_t smem_u32(const void* p) {
    uint32_t a;
    asm("{ .reg .u64 t; cvta.to.shared.u64 t, %1; cvt.u32.u64 %0, t; }" : "=r"(a) : "l"(p));
    return a;
}
__device__ __forceinline__ void cp_async16(uint32_t s, const void* g) {
    asm volatile("cp.async.cg.shared.global [%0], [%1], 16;" :: "r"(s), "l"(g) : "memory");
}
__device__ __forceinline__ void ldsm_x4(uint32_t* r, uint32_t a) {
    asm volatile("ldmatrix.sync.aligned.m8n8.x4.shared.b16 {%0,%1,%2,%3}, [%4];"
                 : "=r"(r[0]), "=r"(r[1]), "=r"(r[2]), "=r"(r[3]) : "r"(a));
}
__device__ __forceinline__ void ldsm_x2(uint32_t* r, uint32_t a) {
    asm volatile("ldmatrix.sync.aligned.m8n8.x2.shared.b16 {%0,%1}, [%2];"
                 : "=r"(r[0]), "=r"(r[1]) : "r"(a));
}
__device__ __forceinline__ void mma16816(float* c, const uint32_t* a, const uint32_t* b) {
    asm volatile(
        "mma.sync.aligned.m16n8k16.row.col.f32.bf16.bf16.f32 "
        "{%0,%1,%2,%3}, {%4,%5,%6,%7}, {%8,%9}, {%0,%1,%2,%3};"
        : "+f"(c[0]), "+f"(c[1]), "+f"(c[2]), "+f"(c[3])
        : "r"(a[0]), "r"(a[1]), "r"(a[2]), "r"(a[3]), "r"(b[0]), "r"(b[1]));
}

// ============ merged-pass warp-MMA GEMM ============
// C(fp32, M x ldc) = 3-term split(A) @ split(B)^T:  AhBh + AhBl + AlBh, fp32 acc.
// Per K-chunk (BK=32) all 4 tiles (Ah,Al,Bh,Bl) staged once; combined 128B rows:
// chunks 0-3 = hi, 4-7 = lo, phys chunk = logical ^ (row&7) (XOR swizzle, 128B rows).
// Block 128x128, 8 warps (2x4), warp tile 64x32, 3-stage cp.async pipeline.
#define BMt 128
#define BNt 128
#define STG_SZ 32768u   // A-comb 16KB + B-comb 16KB
#define NSTAGE 3

__global__ __launch_bounds__(256, 2) void mma_gemm_k(
    float* __restrict__ C,
    const bf16* __restrict__ Ah, const bf16* __restrict__ Al,
    const bf16* __restrict__ Bh, const bf16* __restrict__ Bl,
    int Kt, int ldc, ll sAb, ll sBb, ll sCb) {
    extern __shared__ char smem[];
    uint32_t sbase = smem_u32(smem);
    int tid = threadIdx.x, wid = tid >> 5, lane = tid & 31;
    int b = blockIdx.z;
    int m0 = blockIdx.y * BMt, n0 = blockIdx.x * BNt;

    const bf16* A0 = Ah + (size_t)b * sAb + (size_t)m0 * Kt;
    const bf16* A1 = Al + (size_t)b * sAb + (size_t)m0 * Kt;
    const bf16* B0 = Bh + (size_t)b * sBb + (size_t)n0 * Kt;
    const bf16* B1 = Bl + (size_t)b * sBb + (size_t)n0 * Kt;

    // ---- cp.async mapping: row = tid>>1 (0..127), cq = tid&1 ----
    int row = tid >> 1, cq = tid & 1, rx = row & 7;
    size_t   gA0 = (size_t)row * Kt + cq * 8;          // chunk cq
    size_t   gA1 = gA0 + 16;                           // chunk cq+2
    uint32_t dh0 = row * 128 + ((cq)     ^ rx) * 16;
    uint32_t dh1 = row * 128 + ((cq + 2) ^ rx) * 16;
    uint32_t dl0 = row * 128 + ((cq + 4) ^ rx) * 16;
    uint32_t dl1 = row * 128 + ((cq + 6) ^ rx) * 16;

    // ---- ldmatrix per-lane offsets ----
    int warp_m = wid >> 2, warp_n = wid & 3;
    int rl = lane & 15, cl = lane >> 4, arx = lane & 7;
    int rb = lane & 7,  cb = (lane >> 3) & 1;
    uint32_t arow[4], brow[4];
#pragma unroll
    for (int i = 0; i < 4; i++) arow[i] = (warp_m * 64 + i * 16 + rl) * 128;
#pragma unroll
    for (int j = 0; j < 4; j++) brow[j] = (warp_n * 32 + j * 8 + rb) * 128;

    float acc[4][4][4];
#pragma unroll
    for (int i = 0; i < 4; i++)
#pragma unroll
        for (int j = 0; j < 4; j++)
#pragma unroll
            for (int q = 0; q < 4; q++) acc[i][j][q] = 0.f;

    const int NC = Kt >> 5;

#define ISSUE(c_) do {                                                        \
    size_t ko_ = (size_t)(c_) * 32;                                           \
    uint32_t st_ = sbase + ((c_) % NSTAGE) * STG_SZ;                          \
    cp_async16(st_ + dh0, A0 + ko_ + gA0);                                    \
    cp_async16(st_ + dh1, A0 + ko_ + gA1);                                    \
    cp_async16(st_ + dl0, A1 + ko_ + gA0);                                    \
    cp_async16(st_ + dl1, A1 + ko_ + gA1);                                    \
    cp_async16(st_ + 16384u + dh0, B0 + ko_ + gA0);                           \
    cp_async16(st_ + 16384u + dh1, B0 + ko_ + gA1);                           \
    cp_async16(st_ + 16384u + dl0, B1 + ko_ + gA0);                           \
    cp_async16(st_ + 16384u + dl1, B1 + ko_ + gA1);                           \
    asm volatile("cp.async.commit_group;" ::: "memory");                      \
} while (0)

    ISSUE(0); ISSUE(1);

    for (int c = 0; c < NC; c++) {
        if (c + 2 < NC) {
            ISSUE(c + 2);
            asm volatile("cp.async.wait_group 2;" ::: "memory");
        } else if (c + 1 < NC) {
            asm volatile("cp.async.wait_group 1;" ::: "memory");
        } else {
            asm volatile("cp.async.wait_group 0;" ::: "memory");
        }
        __syncthreads();

        uint32_t sa = sbase + (c % NSTAGE) * STG_SZ;
        uint32_t sb = sa + 16384u;
#pragma unroll
        for (int kk = 0; kk < 2; kk++) {
            uint32_t bh[4][2], blo[4][2], af[4][4];
#pragma unroll
            for (int j = 0; j < 4; j++)
                ldsm_x2(bh[j], sb + brow[j] + (((kk * 2 + cb)     ^ rb) << 4));
#pragma unroll
            for (int j = 0; j < 4; j++)
                ldsm_x2(blo[j], sb + brow[j] + (((kk * 2 + cb + 4) ^ rb) << 4));
#pragma unroll
            for (int i = 0; i < 4; i++)
                ldsm_x4(af[i], sa + arow[i] + (((kk * 2 + cl)     ^ arx) << 4));
#pragma unroll
            for (int i = 0; i < 4; i++)
#pragma unroll
                for (int j = 0; j < 4; j++) mma16816(acc[i][j], af[i], bh[j]);
#pragma unroll
            for (int i = 0; i < 4; i++)
#pragma unroll
                for (int j = 0; j < 4; j++) mma16816(acc[i][j], af[i], blo[j]);
#pragma unroll
            for (int i = 0; i < 4; i++)
                ldsm_x4(af[i], sa + arow[i] + (((kk * 2 + cl + 4) ^ arx) << 4));
#pragma unroll
            for (int i = 0; i < 4; i++)
#pragma unroll
                for (int j = 0; j < 4; j++) mma16816(acc[i][j], af[i], bh[j]);
        }
        __syncthreads();
    }

    // ---- epilogue: direct float2 stores ----
    float* Cb = C + (size_t)b * sCb;
#pragma unroll
    for (int i = 0; i < 4; i++) {
        int m = m0 + warp_m * 64 + i * 16 + (lane >> 2);
#pragma unroll
        for (int j = 0; j < 4; j++) {
            int n = n0 + warp_n * 32 + j * 8 + (lane & 3) * 2;
            *(float2*)&Cb[(size_t)m * ldc + n]       = make_float2(acc[i][j][0], acc[i][j][1]);
            *(float2*)&Cb[(size_t)(m + 8) * ldc + n] = make_float2(acc[i][j][2], acc[i][j][3]);
        }
    }
}

// ---------------- bf16 split helper ----------------
__device__ __forceinline__ void split2(float v, bf16& h, bf16& l) {
    h = __float2bfloat16(v);
    l = __float2bfloat16(v - __bfloat162float(h));
}

// ---------------- x -> bf16 hi/lo (straight + transposed) ----------------
__global__ __launch_bounds__(256) void convx_k(const float* __restrict__ x,
                                               bf16* __restrict__ xh, bf16* __restrict__ xl,
                                               bf16* __restrict__ xth, bf16* __restrict__ xtl) {
    __shared__ float ts[32][33];
    int b = blockIdx.z;
    int t0 = blockIdx.x * 32, d0 = blockIdx.y * 32;
    int tx = threadIdx.x & 31, ty = threadIdx.x >> 5;
#pragma unroll
    for (int i = 0; i < 4; i++) {
        int t = ty * 4 + i;
        size_t o = ((size_t)b * Tt + t0 + t) * Dd + d0 + tx;
        float v = x[o];
        ts[t][tx] = v;
        bf16 h, l; split2(v, h, l);
        xh[o] = h; xl[o] = l;
    }
    __syncthreads();
#pragma unroll
    for (int i = 0; i < 4; i++) {
        int d = ty * 4 + i;
        float v = ts[tx][d];
        bf16 h, l; split2(v, h, l);
        size_t o = ((size_t)b * Dd + d0 + d) * Tt + t0 + tx;
        xth[o] = h; xtl[o] = l;
    }
}

// ---------------- weight fp32 -> bf16 hi/lo ----------------
__global__ __launch_bounds__(256) void convw_k(const float* __restrict__ W,
                                               bf16* __restrict__ Wh, bf16* __restrict__ Wl) {
    for (int i = blockIdx.x * 256 + threadIdx.x; i < Dd * Dd; i += gridDim.x * 256) {
        bf16 h, l; split2(W[i], h, l);
        Wh[i] = h; Wl[i] = l;
    }
}

// ---------------- gather x rows at idx, split to bf16 hi/lo ----------------
__global__ __launch_bounds__(256) void gather_xs_k(bf16* __restrict__ xsh,
                                                   bf16* __restrict__ xsl,
                                                   const float4* __restrict__ x,
                                                   const int* __restrict__ idx, int u) {
    int b = blockIdx.x / u, j = blockIdx.x % u;
    int t = idx[j];
    float4 v = x[((size_t)b * Tt + t) * (Dd / 4) + threadIdx.x];
    size_t o = ((size_t)b * u + j) * Dd + threadIdx.x * 4;
    bf16 h, l;
    split2(v.x, h, l); xsh[o + 0] = h; xsl[o + 0] = l;
    split2(v.y, h, l); xsh[o + 1] = h; xsl[o + 1] = l;
    split2(v.z, h, l); xsh[o + 2] = h; xsl[o + 2] = l;
    split2(v.w, h, l); xsh[o + 3] = h; xsl[o + 3] = l;
}

// ---------------- small fp32 SIMT GEMM (optional bf16-split output) ----------------
template <bool NT, bool SPLIT>
__global__ __launch_bounds__(256) void gemm_k(
    float* __restrict__ C, const float* __restrict__ A, const float* __restrict__ B,
    int M, int N, int K, int lda, int ldb, int ldc,
    ll sAb, ll sAh, ll sBb, ll sBh, ll sCb, ll sCh, int nh, float alpha,
    bf16* __restrict__ Ch, bf16* __restrict__ Cl) {
    int z = blockIdx.z;
    int bb = z / nh, hh = z - bb * nh;
    A += bb * sAb + hh * sAh;
    B += bb * sBb + hh * sBh;
    C += bb * sCb + hh * sCh;
    if (SPLIT) { Ch += bb * sCb + hh * sCh; Cl += bb * sCb + hh * sCh; }

    int m0 = blockIdx.y * 64, n0 = blockIdx.x * 128;
    __shared__ float As[16][64];
    __shared__ float Bs[16][128];

    int tid = threadIdx.x;
    int tm = tid >> 4, tn = tid & 15;
    int ar = tid >> 2, ak = (tid & 3) << 2;

    unsigned long long acc[2][8];
#pragma unroll
    for (int p = 0; p < 2; p++)
#pragma unroll
        for (int j = 0; j < 8; j++) acc[p][j] = 0ull;

    for (int k0 = 0; k0 < K; k0 += 16) {
        float4 av = make_float4(0.f, 0.f, 0.f, 0.f);
        if (m0 + ar < M) av = *(const float4*)(A + (size_t)(m0 + ar) * lda + (k0 + ak));
        As[ak + 0][ar] = av.x; As[ak + 1][ar] = av.y;
        As[ak + 2][ar] = av.z; As[ak + 3][ar] = av.w;

        if (NT) {
#pragma unroll
            for (int rr = 0; rr < 2; rr++) {
                int n = n0 + ar + rr * 64;
                float4 bv = make_float4(0.f, 0.f, 0.f, 0.f);
                if (n < N) bv = *(const float4*)(B + (size_t)n * ldb + (k0 + ak));
                Bs[ak + 0][ar + rr * 64] = bv.x; Bs[ak + 1][ar + rr * 64] = bv.y;
                Bs[ak + 2][ar + rr * 64] = bv.z; Bs[ak + 3][ar + rr * 64] = bv.w;
            }
        } else {
            int kk = tid >> 4, n8 = (tid & 15) << 3;
#pragma unroll
            for (int q = 0; q < 2; q++) {
                int n = n0 + n8 + q * 4;
                float4 bv = make_float4(0.f, 0.f, 0.f, 0.f);
                if (n < N) bv = *(const float4*)(B + (size_t)(k0 + kk) * ldb + n);
                *(float4*)&Bs[kk][n8 + q * 4] = bv;
            }
        }
        __syncthreads();

#pragma unroll
        for (int k = 0; k < 16; k++) {
            unsigned long long a0 = *(const unsigned long long*)&As[k][tm * 4];
            unsigned long long a1 = *(const unsigned long long*)&As[k][tm * 4 + 2];
            float4 blo = *(const float4*)&Bs[k][tn * 8];
            float4 bhi = *(const float4*)&Bs[k][tn * 8 + 4];
            float bv[8] = {blo.x, blo.y, blo.z, blo.w, bhi.x, bhi.y, bhi.z, bhi.w};
#pragma unroll
            for (int j = 0; j < 8; j++) {
                unsigned int bi = __float_as_uint(bv[j]);
                unsigned long long bp;
                asm("mov.b64 %0, {%1, %1};" : "=l"(bp) : "r"(bi));
                asm("fma.rn.f32x2 %0, %1, %2, %0;" : "+l"(acc[0][j]) : "l"(a0), "l"(bp));
                asm("fma.rn.f32x2 %0, %1, %2, %0;" : "+l"(acc[1][j]) : "l"(a1), "l"(bp));
            }
        }
        __syncthreads();
    }

#pragma unroll
    for (int p = 0; p < 2; p++) {
#pragma unroll
        for (int i = 0; i < 2; i++) {
            int m = m0 + tm * 4 + p * 2 + i;
            if (m < M) {
#pragma unroll
                for (int j = 0; j < 8; j++) {
                    int n = n0 + tn * 8 + j;
                    if (n < N) {
                        float2 c2 = *(float2*)&acc[p][j];
                        float v = alpha * (i == 0 ? c2.x : c2.y);
                        if (SPLIT) {
                            bf16 h, l; split2(v, h, l);
                            Ch[(size_t)m * ldc + n] = h;
                            Cl[(size_t)m * ldc + n] = l;
                        } else {
                            C[(size_t)m * ldc + n] = v;
                        }
                    }
                }
            }
        }
    }
}

// ---------------- softmax: write UNNORMALIZED exp hi/lo + row sums ----------------
__global__ __launch_bounds__(256) void softmax_k(const float* __restrict__ s,
                                                 bf16* __restrict__ ah, bf16* __restrict__ al,
                                                 float* __restrict__ rsum, int Hu, int mp) {
    __shared__ float red[256];
    int b = blockIdx.x / Hu, r = blockIdx.x % Hu;
    size_t base = ((size_t)b * mp + r) * Tt;
    int tid = threadIdx.x;
    float m = -3.4e38f;
    for (int t = tid; t < Tt; t += 256) m = fmaxf(m, s[base + t]);
    red[tid] = m; __syncthreads();
    for (int o = 128; o > 0; o >>= 1) {
        if (tid < o) red[tid] = fmaxf(red[tid], red[tid + o]);
        __syncthreads();
    }
    float mx = red[0];
    __syncthreads();
    float sum = 0.f;
    for (int t = tid; t < Tt; t += 256) {
        float e = __expf(s[base + t] - mx);
        sum += e;
        bf16 h, l; split2(e, h, l);
        ah[base + t] = h; al[base + t] = l;
    }
    red[tid] = sum; __syncthreads();
    for (int o = 128; o > 0; o >>= 1) {
        if (tid < o) red[tid] += red[tid + o];
        __syncthreads();
    }
    if (tid == 0) rsum[blockIdx.x] = red[0];
}

// ---------------- ctx -> per-token rows + mean row (normalize by rsum) ----------------
__global__ __launch_bounds__(64) void ctxrow_mean_k(float* __restrict__ cr,
                                                    const float* __restrict__ ctx,
                                                    const float* __restrict__ rsum,
                                                    int u, int Hu) {
    int b = blockIdx.x, h = blockIdx.y, d = threadIdx.x;
    float s = 0.f;
    for (int j = 0; j < u; j++) {
        float inv = 1.f / rsum[b * Hu + h * u + j];
        float v = ctx[((size_t)(b * Hh + h) * u + j) * DHh + d] * inv;
        cr[((size_t)b * (u + 1) + j) * Dd + h * DHh + d] = v;
        s += v;
    }
    cr[((size_t)b * (u + 1) + u) * Dd + h * DHh + d] = s / (float)u;
}

// ---------------- broadcast fill + scatter ----------------
__global__ __launch_bounds__(256) void fill_k(float4* __restrict__ y,
                                              const float4* __restrict__ ys,
                                              const float4* __restrict__ bo, int u) {
    int b = blockIdx.x / Tt;
    float4 v = ys[((size_t)b * (u + 1) + u) * 256 + threadIdx.x];
    float4 bb = bo[threadIdx.x];
    y[(size_t)blockIdx.x * 256 + threadIdx.x] =
        make_float4(v.x + bb.x, v.y + bb.y, v.z + bb.z, v.w + bb.w);
}
__global__ __launch_bounds__(256) void scatter_k(float4* __restrict__ y,
                                                 const float4* __restrict__ ys,
                                                 const float4* __restrict__ bo,
                                                 const int* __restrict__ idx, int u) {
    int b = blockIdx.x, j = blockIdx.y;
    int t = idx[j];
    float4 v = ys[((size_t)b * (u + 1) + j) * 256 + threadIdx.x];
    float4 bb = bo[threadIdx.x];
    y[((size_t)b * Tt + t) * 256 + threadIdx.x] =
        make_float4(v.x + bb.x, v.y + bb.y, v.z + bb.z, v.w + bb.w);
}

// ---------------- launch ----------------
extern "C" void kernel_launch(void* const* d_in, const int* in_sizes, int n_in,
                              void* d_out, int out_size) {
    const float* x  = (const float*)d_in[0];
    const float* Wq = (const float*)d_in[1];
    const float* Wk = (const float*)d_in[2];
    const float* Wv = (const float*)d_in[3];
    const float* Wo = (const float*)d_in[4];
    const float* bo = (const float*)d_in[5];
    const int* idx  = (const int*)d_in[6];
    int u = in_sizes[6];
    if (u > UMAX) u = UMAX;
    if (u < 1) u = 1;
    float* y = (float*)d_out;

    float *Qs, *sc, *rsum, *wx, *ctx, *cr, *ys;
    bf16 *xsh, *xsl, *Wqh, *Wql, *Qth, *Qtl, *xh, *xl, *xth, *xtl, *ah, *al;
    cudaGetSymbolAddress((void**)&xsh, g_xsh);
    cudaGetSymbolAddress((void**)&xsl, g_xsl);
    cudaGetSymbolAddress((void**)&Qs,  g_Qs);
    cudaGetSymbolAddress((void**)&Wqh, g_Wqh);
    cudaGetSymbolAddress((void**)&Wql, g_Wql);
    cudaGetSymbolAddress((void**)&sc,  g_sc);
    cudaGetSymbolAddress((void**)&rsum, g_rsum);
    cudaGetSymbolAddress((void**)&wx,  g_wx);
    cudaGetSymbolAddress((void**)&ctx, g_ctx);
    cudaGetSymbolAddress((void**)&cr,  g_cr);
    cudaGetSymbolAddress((void**)&ys,  g_ys);
    cudaGetSymbolAddress((void**)&Qth, g_Qth);
    cudaGetSymbolAddress((void**)&Qtl, g_Qtl);
    cudaGetSymbolAddress((void**)&xh,  g_xh);
    cudaGetSymbolAddress((void**)&xl,  g_xl);
    cudaGetSymbolAddress((void**)&xth, g_xth);
    cudaGetSymbolAddress((void**)&xtl, g_xtl);
    cudaGetSymbolAddress((void**)&ah,  g_ah);
    cudaGetSymbolAddress((void**)&al,  g_al);

    const int Hu = Hh * u;
    const int mp = ((Hu + 127) / 128) * 128;
    const int Bu = Bb * u;
    const int bup = ((Bu + 127) / 128) * 128;   // padded M for step 2
    const float scale = 0.125f;

    const int smem_sz = NSTAGE * (int)STG_SZ;  // 98304
    cudaFuncSetAttribute(mma_gemm_k, cudaFuncAttributeMaxDynamicSharedMemorySize, smem_sz);

    // 0) x -> bf16 hi/lo, straight + transposed; Wq -> hi/lo
    convx_k<<<dim3(Tt / 32, Dd / 32, Bb), 256>>>(x, xh, xl, xth, xtl);
    convw_k<<<512, 256>>>(Wq, Wqh, Wql);

    // 1) gather+split x rows at idx
    gather_xs_k<<<Bb * u, 256>>>(xsh, xsl, (const float4*)x, idx, u);

    // 2) Qs = xs @ Wq^T   (merged-pass MMA; pad rows of xsh/xsl are zero)
    mma_gemm_k<<<dim3(Dd / BNt, bup / BMt, 1), 256, smem_sz>>>(
        Qs, xsh, xsl, Wqh, Wql, Dd, Dd, 0, 0, 0);

    // 3) Qt[b,h] = scale * Qs[b,:,hDH:] @ Wk_h  -> bf16 hi/lo direct (padded layout)
    gemm_k<false, true><<<dim3(Dd / 128, (u + 63) / 64, Bb * Hh), 256>>>(
        nullptr, Qs, Wk, u, Dd, DHh, Dd, Dd, Dd,
        (ll)u * Dd, (ll)DHh, 0, (ll)DHh * Dd, (ll)mp * Dd, (ll)u * Dd, Hh, scale,
        Qth, Qtl);

    // 4) scores[b] = Qt[b] @ x[b]^T   (merged-pass MMA)
    mma_gemm_k<<<dim3(Tt / BNt, mp / BMt, Bb), 256, smem_sz>>>(
        sc, Qth, Qtl, xh, xl, Dd, Tt, (ll)mp * Dd, (ll)Tt * Dd, (ll)mp * Tt);

    // 5) softmax -> unnormalized exp hi/lo + row sums
    softmax_k<<<Bb * Hu, 256>>>(sc, ah, al, rsum, Hu, mp);

    // 6) wx[b] = e[b] @ x[b]   (merged-pass MMA; B = x^T layout)
    mma_gemm_k<<<dim3(Dd / BNt, mp / BMt, Bb), 256, smem_sz>>>(
        wx, ah, al, xth, xtl, Tt, Dd, (ll)mp * Tt, (ll)Dd * Tt, (ll)mp * Dd);

    // 7) ctx[b,h] = wx[b,h] @ Wv_h^T   (fp32 SIMT)
    gemm_k<true, false><<<dim3(1, (u + 63) / 64, Bb * Hh), 256>>>(
        ctx, wx, Wv, u, DHh, Dd, Dd, Dd, DHh,
        (ll)mp * Dd, (ll)u * Dd, 0, (ll)DHh * Dd, (ll)Hu * DHh, (ll)u * DHh, Hh, 1.f,
        nullptr, nullptr);

    // 8) reorder ctx + normalize + mean row
    ctxrow_mean_k<<<dim3(Bb, Hh), 64>>>(cr, ctx, rsum, u, Hu);

    // 9) ys = cr @ Wo^T   (fp32 SIMT)
    gemm_k<true, false><<<dim3(Dd / 128, (u + 64) / 64, Bb), 256>>>(
        ys, cr, Wo, u + 1, Dd, Dd, Dd, Dd, Dd,
        (ll)(u + 1) * Dd, 0, 0, 0, (ll)(u + 1) * Dd, 0, 1, 1.f,
        nullptr, nullptr);

    // 10) broadcast + scatter
    fill_k<<<Bb * Tt, 256>>>((float4*)y, (const float4*)ys, (const float4*)bo, u);
    scatter_k<<<dim3(Bb, u), 256>>>((float4*)y, (const float4*)ys, (const float4*)bo, idx, u);
}

// round 8
// speedup vs baseline: 3.1825x; 1.1750x over previous
#include <cuda_runtime.h>
#include <cuda_bf16.h>
#include <cstdint>

#define Bb   8
#define Tt   4096
#define Dd   1024
#define Hh   16
#define DHh  64
#define UMAX 64
#define MPMAX 1024
#define BUPMAX 512

typedef long long ll;
typedef __nv_bfloat16 bf16;

// ---------------- scratch (static __device__, allocation-free) ----------------
__device__ bf16  g_xsh[Bb * UMAX * Dd];
__device__ bf16  g_xsl[Bb * UMAX * Dd];
__device__ bf16  g_Wqh[Dd * Dd];
__device__ bf16  g_Wql[Dd * Dd];
__device__ bf16  g_WkTh[Dd * Dd];
__device__ bf16  g_WkTl[Dd * Dd];
__device__ bf16  g_Wvh[(Dd + 128) * Dd];     // row-padded for OOB-safe tile loads
__device__ bf16  g_Wvl[(Dd + 128) * Dd];
__device__ bf16  g_Woh[Dd * Dd];
__device__ bf16  g_Wol[Dd * Dd];
__device__ float g_qsp[4 * BUPMAX * Dd];     // step-2 split-K partials
__device__ bf16  g_Qsh[Bb * UMAX * Dd];
__device__ bf16  g_Qsl[Bb * UMAX * Dd];
__device__ bf16  g_Qth[(size_t)Bb * MPMAX * Dd];
__device__ bf16  g_Qtl[(size_t)Bb * MPMAX * Dd];
__device__ bf16  g_xh[(size_t)Bb * Tt * Dd];
__device__ bf16  g_xl[(size_t)Bb * Tt * Dd];
__device__ bf16  g_xth[(size_t)Bb * Dd * Tt];
__device__ bf16  g_xtl[(size_t)Bb * Dd * Tt];
__device__ float g_sc[(size_t)Bb * MPMAX * Tt];
__device__ bf16  g_ah[(size_t)Bb * MPMAX * Tt];
__device__ bf16  g_al[(size_t)Bb * MPMAX * Tt];
__device__ float g_rsum[Bb * Hh * UMAX];
__device__ bf16  g_wxh[(size_t)Bb * MPMAX * Dd];
__device__ bf16  g_wxl[(size_t)Bb * MPMAX * Dd];
__device__ float g_ctx[Bb * Hh * UMAX * DHh];
__device__ bf16  g_crh[Bb * (UMAX + 2) * Dd];
__device__ bf16  g_crl[Bb * (UMAX + 2) * Dd];
__device__ float g_ys[Bb * (UMAX + 1) * Dd];

// ---------------- PTX helpers (sm_80/sm_90 portable only) ----------------
__device__ __forceinline__ uint32_t smem_u32(const void* p) {
    uint32_t a;
    asm("{ .reg .u64 t; cvta.to.shared.u64 t, %1; cvt.u32.u64 %0, t; }" : "=r"(a) : "l"(p));
    return a;
}
__device__ __forceinline__ void cp_async16(uint32_t s, const void* g) {
    asm volatile("cp.async.cg.shared.global [%0], [%1], 16;" :: "r"(s), "l"(g) : "memory");
}
__device__ __forceinline__ void ldsm_x4(uint32_t* r, uint32_t a) {
    asm volatile("ldmatrix.sync.aligned.m8n8.x4.shared.b16 {%0,%1,%2,%3}, [%4];"
                 : "=r"(r[0]), "=r"(r[1]), "=r"(r[2]), "=r"(r[3]) : "r"(a));
}
__device__ __forceinline__ void ldsm_x2(uint32_t* r, uint32_t a) {
    asm volatile("ldmatrix.sync.aligned.m8n8.x2.shared.b16 {%0,%1}, [%2];"
                 : "=r"(r[0]), "=r"(r[1]) : "r"(a));
}
__device__ __forceinline__ void mma16816(float* c, const uint32_t* a, const uint32_t* b) {
    asm volatile(
        "mma.sync.aligned.m16n8k16.row.col.f32.bf16.bf16.f32 "
        "{%0,%1,%2,%3}, {%4,%5,%6,%7}, {%8,%9}, {%0,%1,%2,%3};"
        : "+f"(c[0]), "+f"(c[1]), "+f"(c[2]), "+f"(c[3])
        : "r"(a[0]), "r"(a[1]), "r"(a[2]), "r"(a[3]), "r"(b[0]), "r"(b[1]));
}

__device__ __forceinline__ void split2(float v, bf16& h, bf16& l) {
    h = __float2bfloat16(v);
    l = __float2bfloat16(v - __bfloat162float(h));
}

// ============ generalized merged-pass warp-MMA GEMM ============
// C = 3-term split(A) @ split(B)^T  (AhBh + AhBl + AlBh, fp32 acc).
// A: (M x Kext) rows at stride lda; B: (N x Kext) rows at stride ldb.
// z = ((bb*nh + hh)*KS + ks); K window = [ks*Kext, (ks+1)*Kext).
// EPI=0: fp32 C.  EPI=1: bf16 hi/lo split C (Ch, Cl).
// Block 128x128, BK=32, 8 warps (2x4), warp tile 64x32, 3-stage cp.async.
#define BMt 128
#define BNt 128
#define STG_SZ 32768u
#define NSTAGE 3

template <int EPI>
__global__ __launch_bounds__(256, 2) void mma_gemm_k(
    float* __restrict__ C, bf16* __restrict__ Ch, bf16* __restrict__ Cl,
    const bf16* __restrict__ Ah, const bf16* __restrict__ Al,
    const bf16* __restrict__ Bh, const bf16* __restrict__ Bl,
    int Kext, int lda, int ldb, int ldc, int Mreal, int Nreal,
    ll sAb, ll sAh, ll sBb, ll sBh, ll sCb, ll sCh,
    int nh, int KS, ll sCs) {
    extern __shared__ char smem[];
    uint32_t sbase = smem_u32(smem);
    int tid = threadIdx.x, wid = tid >> 5, lane = tid & 31;
    int z = blockIdx.z;
    int ks = z % KS, bh2 = z / KS;
    int hh = bh2 % nh, bb = bh2 / nh;
    int m0 = blockIdx.y * BMt, n0 = blockIdx.x * BNt;

    const bf16* A0 = Ah + bb * sAb + hh * sAh + (ll)ks * Kext + (size_t)m0 * lda;
    const bf16* A1 = Al + bb * sAb + hh * sAh + (ll)ks * Kext + (size_t)m0 * lda;
    const bf16* B0 = Bh + bb * sBb + hh * sBh + (ll)ks * Kext + (size_t)n0 * ldb;
    const bf16* B1 = Bl + bb * sBb + hh * sBh + (ll)ks * Kext + (size_t)n0 * ldb;

    // cp.async mapping: row = tid>>1 (0..127), cq = tid&1
    int row = tid >> 1, cq = tid & 1, rx = row & 7;
    size_t   gA0 = (size_t)row * lda + cq * 8, gA1 = gA0 + 16;
    size_t   gB0 = (size_t)row * ldb + cq * 8, gB1 = gB0 + 16;
    uint32_t dh0 = row * 128 + ((cq)     ^ rx) * 16;
    uint32_t dh1 = row * 128 + ((cq + 2) ^ rx) * 16;
    uint32_t dl0 = row * 128 + ((cq + 4) ^ rx) * 16;
    uint32_t dl1 = row * 128 + ((cq + 6) ^ rx) * 16;

    // ldmatrix per-lane offsets
    int warp_m = wid >> 2, warp_n = wid & 3;
    int rl = lane & 15, cl = lane >> 4, arx = lane & 7;
    int rb = lane & 7,  cb = (lane >> 3) & 1;
    uint32_t arow[4], brow[4];
#pragma unroll
    for (int i = 0; i < 4; i++) arow[i] = (warp_m * 64 + i * 16 + rl) * 128;
#pragma unroll
    for (int j = 0; j < 4; j++) brow[j] = (warp_n * 32 + j * 8 + rb) * 128;

    float acc[4][4][4];
#pragma unroll
    for (int i = 0; i < 4; i++)
#pragma unroll
        for (int j = 0; j < 4; j++)
#pragma unroll
            for (int q = 0; q < 4; q++) acc[i][j][q] = 0.f;

    const int NC = Kext >> 5;

#define ISSUE(c_) do {                                                        \
    size_t ko_ = (size_t)(c_) * 32;                                           \
    uint32_t st_ = sbase + ((c_) % NSTAGE) * STG_SZ;                          \
    cp_async16(st_ + dh0, A0 + ko_ + gA0);                                    \
    cp_async16(st_ + dh1, A0 + ko_ + gA1);                                    \
    cp_async16(st_ + dl0, A1 + ko_ + gA0);                                    \
    cp_async16(st_ + dl1, A1 + ko_ + gA1);                                    \
    cp_async16(st_ + 16384u + dh0, B0 + ko_ + gB0);                           \
    cp_async16(st_ + 16384u + dh1, B0 + ko_ + gB1);                           \
    cp_async16(st_ + 16384u + dl0, B1 + ko_ + gB0);                           \
    cp_async16(st_ + 16384u + dl1, B1 + ko_ + gB1);                           \
    asm volatile("cp.async.commit_group;" ::: "memory");                      \
} while (0)

    ISSUE(0);
    if (NC > 1) ISSUE(1);

    for (int c = 0; c < NC; c++) {
        if (c + 1 < NC) asm volatile("cp.async.wait_group 1;" ::: "memory");
        else            asm volatile("cp.async.wait_group 0;" ::: "memory");
        __syncthreads();
        if (c + 2 < NC) ISSUE(c + 2);

        uint32_t sa = sbase + (c % NSTAGE) * STG_SZ;
        uint32_t sb = sa + 16384u;
#pragma unroll
        for (int kk = 0; kk < 2; kk++) {
            uint32_t bh[4][2], blo[4][2], af[4][4];
#pragma unroll
            for (int j = 0; j < 4; j++)
                ldsm_x2(bh[j], sb + brow[j] + (((kk * 2 + cb)     ^ rb) << 4));
#pragma unroll
            for (int j = 0; j < 4; j++)
                ldsm_x2(blo[j], sb + brow[j] + (((kk * 2 + cb + 4) ^ rb) << 4));
#pragma unroll
            for (int i = 0; i < 4; i++)
                ldsm_x4(af[i], sa + arow[i] + (((kk * 2 + cl)     ^ arx) << 4));
#pragma unroll
            for (int i = 0; i < 4; i++)
#pragma unroll
                for (int j = 0; j < 4; j++) mma16816(acc[i][j], af[i], bh[j]);
#pragma unroll
            for (int i = 0; i < 4; i++)
#pragma unroll
                for (int j = 0; j < 4; j++) mma16816(acc[i][j], af[i], blo[j]);
#pragma unroll
            for (int i = 0; i < 4; i++)
                ldsm_x4(af[i], sa + arow[i] + (((kk * 2 + cl + 4) ^ arx) << 4));
#pragma unroll
            for (int i = 0; i < 4; i++)
#pragma unroll
                for (int j = 0; j < 4; j++) mma16816(acc[i][j], af[i], bh[j]);
        }
        __syncthreads();
    }

    // ---- epilogue ----
    ll cbase = bb * sCb + hh * sCh + (ll)ks * sCs;
#pragma unroll
    for (int i = 0; i < 4; i++) {
        int m = m0 + warp_m * 64 + i * 16 + (lane >> 2);
#pragma unroll
        for (int j = 0; j < 4; j++) {
            int n = n0 + warp_n * 32 + j * 8 + (lane & 3) * 2;
            if (n < Nreal) {
#pragma unroll
                for (int p = 0; p < 2; p++) {
                    int mm = m + p * 8;
                    if (mm < Mreal) {
                        if (EPI == 0) {
                            *(float2*)&C[cbase + (size_t)mm * ldc + n] =
                                make_float2(acc[i][j][p * 2], acc[i][j][p * 2 + 1]);
                        } else {
                            bf16 h0, l0, h1, l1;
                            split2(acc[i][j][p * 2], h0, l0);
                            split2(acc[i][j][p * 2 + 1], h1, l1);
                            __nv_bfloat162 hp, lp;
                            hp.x = h0; hp.y = h1; lp.x = l0; lp.y = l1;
                            *(__nv_bfloat162*)&Ch[cbase + (size_t)mm * ldc + n] = hp;
                            *(__nv_bfloat162*)&Cl[cbase + (size_t)mm * ldc + n] = lp;
                        }
                    }
                }
            }
        }
    }
}

// ---------------- x -> bf16 hi/lo (straight + transposed) ----------------
__global__ __launch_bounds__(256) void convx_k(const float* __restrict__ x,
                                               bf16* __restrict__ xh, bf16* __restrict__ xl,
                                               bf16* __restrict__ xth, bf16* __restrict__ xtl) {
    __shared__ float ts[32][33];
    int b = blockIdx.z;
    int t0 = blockIdx.x * 32, d0 = blockIdx.y * 32;
    int tx = threadIdx.x & 31, ty = threadIdx.x >> 5;
#pragma unroll
    for (int i = 0; i < 4; i++) {
        int t = ty * 4 + i;
        size_t o = ((size_t)b * Tt + t0 + t) * Dd + d0 + tx;
        float v = x[o];
        ts[t][tx] = v;
        bf16 h, l; split2(v, h, l);
        xh[o] = h; xl[o] = l;
    }
    __syncthreads();
#pragma unroll
    for (int i = 0; i < 4; i++) {
        int d = ty * 4 + i;
        float v = ts[tx][d];
        bf16 h, l; split2(v, h, l);
        size_t o = ((size_t)b * Dd + d0 + d) * Tt + t0 + tx;
        xth[o] = h; xtl[o] = l;
    }
}

// ---------------- weight fp32 -> bf16 hi/lo (row-major) ----------------
__global__ __launch_bounds__(256) void convw_k(const float* __restrict__ W,
                                               bf16* __restrict__ Wh, bf16* __restrict__ Wl) {
    for (int i = blockIdx.x * 256 + threadIdx.x; i < Dd * Dd; i += gridDim.x * 256) {
        bf16 h, l; split2(W[i], h, l);
        Wh[i] = h; Wl[i] = l;
    }
}

// ---------------- weight fp32 -> transposed + scaled bf16 hi/lo ----------------
__global__ __launch_bounds__(256) void convwT_k(const float* __restrict__ W,
                                                bf16* __restrict__ Wh, bf16* __restrict__ Wl,
                                                float alpha) {
    __shared__ float ts[32][33];
    int r0 = blockIdx.x * 32, c0 = blockIdx.y * 32;
    int tx = threadIdx.x & 31, ty = threadIdx.x >> 5;
#pragma unroll
    for (int i = 0; i < 4; i++) {
        int r = ty * 4 + i;
        ts[r][tx] = W[(size_t)(r0 + r) * Dd + c0 + tx];
    }
    __syncthreads();
#pragma unroll
    for (int i = 0; i < 4; i++) {
        int c = ty * 4 + i;
        bf16 h, l; split2(alpha * ts[tx][c], h, l);
        size_t o = (size_t)(c0 + c) * Dd + r0 + tx;
        Wh[o] = h; Wl[o] = l;
    }
}

// ---------------- gather x rows at idx, split to bf16 hi/lo ----------------
__global__ __launch_bounds__(256) void gather_xs_k(bf16* __restrict__ xsh,
                                                   bf16* __restrict__ xsl,
                                                   const float4* __restrict__ x,
                                                   const int* __restrict__ idx, int u) {
    int b = blockIdx.x / u, j = blockIdx.x % u;
    int t = idx[j];
    float4 v = x[((size_t)b * Tt + t) * (Dd / 4) + threadIdx.x];
    size_t o = ((size_t)b * u + j) * Dd + threadIdx.x * 4;
    bf16 h, l;
    split2(v.x, h, l); xsh[o + 0] = h; xsl[o + 0] = l;
    split2(v.y, h, l); xsh[o + 1] = h; xsl[o + 1] = l;
    split2(v.z, h, l); xsh[o + 2] = h; xsl[o + 2] = l;
    split2(v.w, h, l); xsh[o + 3] = h; xsl[o + 3] = l;
}

// ---------------- split-K reduce -> bf16 hi/lo ----------------
__global__ __launch_bounds__(256) void redsplit_k(const float* __restrict__ p,
                                                  bf16* __restrict__ oh, bf16* __restrict__ ol,
                                                  int n, int stride) {
    for (int i = blockIdx.x * 256 + threadIdx.x; i < n; i += gridDim.x * 256) {
        float s = p[i] + p[i + stride] + p[i + 2 * stride] + p[i + 3 * stride];
        bf16 h, l; split2(s, h, l);
        oh[i] = h; ol[i] = l;
    }
}

// ---------------- softmax: UNNORMALIZED exp hi/lo + row sums ----------------
__global__ __launch_bounds__(256) void softmax_k(const float* __restrict__ s,
                                                 bf16* __restrict__ ah, bf16* __restrict__ al,
                                                 float* __restrict__ rsum, int Hu, int mp) {
    __shared__ float red[256];
    int b = blockIdx.x / Hu, r = blockIdx.x % Hu;
    size_t base = ((size_t)b * mp + r) * Tt;
    int tid = threadIdx.x;
    float m = -3.4e38f;
    for (int t = tid; t < Tt; t += 256) m = fmaxf(m, s[base + t]);
    red[tid] = m; __syncthreads();
    for (int o = 128; o > 0; o >>= 1) {
        if (tid < o) red[tid] = fmaxf(red[tid], red[tid + o]);
        __syncthreads();
    }
    float mx = red[0];
    __syncthreads();
    float sum = 0.f;
    for (int t = tid; t < Tt; t += 256) {
        float e = __expf(s[base + t] - mx);
        sum += e;
        bf16 h, l; split2(e, h, l);
        ah[base + t] = h; al[base + t] = l;
    }
    red[tid] = sum; __syncthreads();
    for (int o = 128; o > 0; o >>= 1) {
        if (tid < o) red[tid] += red[tid + o];
        __syncthreads();
    }
    if (tid == 0) rsum[blockIdx.x] = red[0];
}

// ---------------- ctx -> per-token rows (normalized) + mean row, bf16 split ----------------
__global__ __launch_bounds__(64) void ctxrow_mean_k(bf16* __restrict__ crh,
                                                    bf16* __restrict__ crl,
                                                    const float* __restrict__ ctx,
                                                    const float* __restrict__ rsum,
                                                    int u, int Hu) {
    int b = blockIdx.x, h = blockIdx.y, d = threadIdx.x;
    float s = 0.f;
    for (int j = 0; j < u; j++) {
        float inv = 1.f / rsum[b * Hu + h * u + j];
        float v = ctx[((size_t)(b * Hh + h) * u + j) * DHh + d] * inv;
        bf16 hh, ll2; split2(v, hh, ll2);
        size_t o = ((size_t)b * (u + 1) + j) * Dd + h * DHh + d;
        crh[o] = hh; crl[o] = ll2;
        s += v;
    }
    bf16 hh, ll2; split2(s / (float)u, hh, ll2);
    size_t o = ((size_t)b * (u + 1) + u) * Dd + h * DHh + d;
    crh[o] = hh; crl[o] = ll2;
}

// ---------------- broadcast fill + scatter ----------------
__global__ __launch_bounds__(256) void fill_k(float4* __restrict__ y,
                                              const float4* __restrict__ ys,
                                              const float4* __restrict__ bo, int u) {
    int b = blockIdx.x / Tt;
    float4 v = ys[((size_t)b * (u + 1) + u) * 256 + threadIdx.x];
    float4 bb = bo[threadIdx.x];
    y[(size_t)blockIdx.x * 256 + threadIdx.x] =
        make_float4(v.x + bb.x, v.y + bb.y, v.z + bb.z, v.w + bb.w);
}
__global__ __launch_bounds__(256) void scatter_k(float4* __restrict__ y,
                                                 const float4* __restrict__ ys,
                                                 const float4* __restrict__ bo,
                                                 const int* __restrict__ idx, int u) {
    int b = blockIdx.x, j = blockIdx.y;
    int t = idx[j];
    float4 v = ys[((size_t)b * (u + 1) + j) * 256 + threadIdx.x];
    float4 bb = bo[threadIdx.x];
    y[((size_t)b * Tt + t) * 256 + threadIdx.x] =
        make_float4(v.x + bb.x, v.y + bb.y, v.z + bb.z, v.w + bb.w);
}

// ---------------- launch ----------------
extern "C" void kernel_launch(void* const* d_in, const int* in_sizes, int n_in,
                              void* d_out, int out_size) {
    const float* x  = (const float*)d_in[0];
    const float* Wq = (const float*)d_in[1];
    const float* Wk = (const float*)d_in[2];
    const float* Wv = (const float*)d_in[3];
    const float* Wo = (const float*)d_in[4];
    const float* bo = (const float*)d_in[5];
    const int* idx  = (const int*)d_in[6];
    int u = in_sizes[6];
    if (u > UMAX) u = UMAX;
    if (u < 1) u = 1;
    float* y = (float*)d_out;

    float *qsp, *sc, *rsum, *ctx, *ys;
    bf16 *xsh, *xsl, *Wqh, *Wql, *WkTh, *WkTl, *Wvh, *Wvl, *Woh, *Wol;
    bf16 *Qsh, *Qsl, *Qth, *Qtl, *xh, *xl, *xth, *xtl, *ah, *al, *wxh, *wxl, *crh, *crl;
    cudaGetSymbolAddress((void**)&xsh,  g_xsh);
    cudaGetSymbolAddress((void**)&xsl,  g_xsl);
    cudaGetSymbolAddress((void**)&Wqh,  g_Wqh);
    cudaGetSymbolAddress((void**)&Wql,  g_Wql);
    cudaGetSymbolAddress((void**)&WkTh, g_WkTh);
    cudaGetSymbolAddress((void**)&WkTl, g_WkTl);
    cudaGetSymbolAddress((void**)&Wvh,  g_Wvh);
    cudaGetSymbolAddress((void**)&Wvl,  g_Wvl);
    cudaGetSymbolAddress((void**)&Woh,  g_Woh);
    cudaGetSymbolAddress((void**)&Wol,  g_Wol);
    cudaGetSymbolAddress((void**)&qsp,  g_qsp);
    cudaGetSymbolAddress((void**)&Qsh,  g_Qsh);
    cudaGetSymbolAddress((void**)&Qsl,  g_Qsl);
    cudaGetSymbolAddress((void**)&Qth,  g_Qth);
    cudaGetSymbolAddress((void**)&Qtl,  g_Qtl);
    cudaGetSymbolAddress((void**)&xh,   g_xh);
    cudaGetSymbolAddress((void**)&xl,   g_xl);
    cudaGetSymbolAddress((void**)&xth,  g_xth);
    cudaGetSymbolAddress((void**)&xtl,  g_xtl);
    cudaGetSymbolAddress((void**)&sc,   g_sc);
    cudaGetSymbolAddress((void**)&ah,   g_ah);
    cudaGetSymbolAddress((void**)&al,   g_al);
    cudaGetSymbolAddress((void**)&rsum, g_rsum);
    cudaGetSymbolAddress((void**)&wxh,  g_wxh);
    cudaGetSymbolAddress((void**)&wxl,  g_wxl);
    cudaGetSymbolAddress((void**)&ctx,  g_ctx);
    cudaGetSymbolAddress((void**)&crh,  g_crh);
    cudaGetSymbolAddress((void**)&crl,  g_crl);
    cudaGetSymbolAddress((void**)&ys,   g_ys);

    const int Hu = Hh * u;
    const int mp = ((Hu + 127) / 128) * 128;
    const int Bu = Bb * u;
    const int bup = ((Bu + 127) / 128) * 128;
    const float scale = 0.125f;

    const int smem_sz = NSTAGE * (int)STG_SZ;  // 98304
    cudaFuncSetAttribute(mma_gemm_k<0>, cudaFuncAttributeMaxDynamicSharedMemorySize, smem_sz);
    cudaFuncSetAttribute(mma_gemm_k<1>, cudaFuncAttributeMaxDynamicSharedMemorySize, smem_sz);

    // 0) conversions
    convx_k<<<dim3(Tt / 32, Dd / 32, Bb), 256>>>(x, xh, xl, xth, xtl);
    convw_k<<<512, 256>>>(Wq, Wqh, Wql);
    convwT_k<<<dim3(32, 32), 256>>>(Wk, WkTh, WkTl, scale);
    convw_k<<<512, 256>>>(Wv, Wvh, Wvl);
    convw_k<<<512, 256>>>(Wo, Woh, Wol);

    // 1) gather+split x rows at idx
    gather_xs_k<<<Bb * u, 256>>>(xsh, xsl, (const float4*)x, idx, u);

    // 2) Qs partials = xs @ Wq^T   (split-K=4, Kext=256)
    mma_gemm_k<0><<<dim3(Dd / BNt, bup / BMt, 4), 256, smem_sz>>>(
        qsp, nullptr, nullptr, xsh, xsl, Wqh, Wql,
        256, Dd, Dd, Dd, Bu, Dd,
        0, 0, 0, 0, 0, 0, 1, 4, (ll)bup * Dd);

    // 2b) reduce 4 partials -> Qs bf16 hi/lo
    redsplit_k<<<512, 256>>>(qsp, Qsh, Qsl, Bu * Dd, bup * Dd);

    // 3) Qt[b,h] = Qs[b](cols h*64..) @ (scale*Wk_h)  -> bf16 hi/lo, padded layout
    mma_gemm_k<1><<<dim3(Dd / BNt, 1, Bb * Hh), 256, smem_sz>>>(
        nullptr, Qth, Qtl, Qsh, Qsl, WkTh, WkTl,
        DHh, Dd, Dd, Dd, u, Dd,
        (ll)u * Dd, (ll)DHh, 0, (ll)DHh, (ll)mp * Dd, (ll)u * Dd, Hh, 1, 0);

    // 4) scores[b] = Qt[b] @ x[b]^T
    mma_gemm_k<0><<<dim3(Tt / BNt, mp / BMt, Bb), 256, smem_sz>>>(
        sc, nullptr, nullptr, Qth, Qtl, xh, xl,
        Dd, Dd, Dd, Tt, mp, Tt,
        (ll)mp * Dd, 0, (ll)Tt * Dd, 0, (ll)mp * Tt, 0, 1, 1, 0);

    // 5) softmax -> unnormalized exp hi/lo + row sums
    softmax_k<<<Bb * Hu, 256>>>(sc, ah, al, rsum, Hu, mp);

    // 6) wx[b] = e[b] @ x[b]   -> bf16 hi/lo (B = x^T layout)
    mma_gemm_k<1><<<dim3(Dd / BNt, mp / BMt, Bb), 256, smem_sz>>>(
        nullptr, wxh, wxl, ah, al, xth, xtl,
        Tt, Tt, Tt, Dd, mp, Dd,
        (ll)mp * Tt, 0, (ll)Dd * Tt, 0, (ll)mp * Dd, 0, 1, 1, 0);

    // 7) ctx[b,h] = wx[b,h] @ Wv_h^T   (fp32 out)
    mma_gemm_k<0><<<dim3(1, 1, Bb * Hh), 256, smem_sz>>>(
        ctx, nullptr, nullptr, wxh, wxl, Wvh, Wvl,
        Dd, Dd, Dd, DHh, u, DHh,
        (ll)mp * Dd, (ll)u * Dd, 0, (ll)DHh * Dd, (ll)Hh * u * DHh, (ll)u * DHh, Hh, 1, 0);

    // 8) reorder ctx + normalize + mean row -> bf16 split
    ctxrow_mean_k<<<dim3(Bb, Hh), 64>>>(crh, crl, ctx, rsum, u, Hu);

    // 9) ys = cr @ Wo^T   (fp32 out)
    mma_gemm_k<0><<<dim3(Dd / BNt, 1, Bb), 256, smem_sz>>>(
        ys, nullptr, nullptr, crh, crl, Woh, Wol,
        Dd, Dd, Dd, Dd, u + 1, Dd,
        (ll)(u + 1) * Dd, 0, 0, 0, (ll)(u + 1) * Dd, 0, 1, 1, 0);

    // 10) broadcast + scatter
    fill_k<<<Bb * Tt, 256>>>((float4*)y, (const float4*)ys, (const float4*)bo, u);
    scatter_k<<<dim3(Bb, u), 256>>>((float4*)y, (const float4*)ys, (const float4*)bo, idx, u);
}